// round 4
// baseline (speedup 1.0000x reference)
#include <cuda_runtime.h>
#include <cuda_fp16.h>
#include <stdint.h>

// q = cos(2*x[...,:8]+theta); h = relu(q@W1^T); out = h@W2^T
// HMMA (mma.sync m16n8k16 f16->f32) + ldmatrix + cp.async double-buffered pipeline.
// (tcgen05 unavailable: harness compiles via compute_103 virtual arch.)

#define EMBED   512
#define FFN     2048
#define NQ      8
#define BM      128
#define BN      256
#define BK      64
#define NCHUNK  (FFN / BK)     // 32
#define THREADS 512
#define HKB     144            // padded row stride in bytes (72 halves)

// dynamic smem offsets (bytes)
#define HS_OFF(p)   ((p) * (BM * HKB))                    // 2 x 18432
#define W2S_OFF(p)  (2 * BM * HKB + (p) * (BN * HKB))     // 2 x 36864
#define W1S_OFF(p)  (2 * BM * HKB + 2 * BN * HKB + (p) * 2048)
#define SMEM_BYTES  (2 * BM * HKB + 2 * BN * HKB + 2 * 2048)   // 114688

__device__ __half W2h[EMBED * FFN];   // fp16 copy of W2 (2 MB, L2-resident)

__global__ void w2_convert_kernel(const float* __restrict__ W2) {
    int idx = blockIdx.x * 256 + threadIdx.x;
    float2 v = *(const float2*)&W2[idx * 2];
    *(__half2*)&W2h[idx * 2] = __floats2half2_rn(v.x, v.y);
}

__device__ __forceinline__ uint32_t smem_u32(const void* p) {
    uint32_t a;
    asm("{ .reg .u64 t; cvta.to.shared.u64 t, %1; cvt.u32.u64 %0, t; }" : "=r"(a) : "l"(p));
    return a;
}

__device__ __forceinline__ void ldsm_x4(uint32_t* r, uint32_t addr) {
    asm volatile("ldmatrix.sync.aligned.m8n8.x4.shared.b16 {%0,%1,%2,%3}, [%4];"
                 : "=r"(r[0]), "=r"(r[1]), "=r"(r[2]), "=r"(r[3]) : "r"(addr));
}

__device__ __forceinline__ void cp16(uint32_t dst, const void* src) {
    asm volatile("cp.async.cg.shared.global [%0], [%1], 16;" :: "r"(dst), "l"(src));
}

__device__ __forceinline__ void mma16816(float* c, const uint32_t* a,
                                         uint32_t b0, uint32_t b1) {
    asm volatile(
        "mma.sync.aligned.m16n8k16.row.col.f32.f16.f16.f32 "
        "{%0,%1,%2,%3}, {%4,%5,%6,%7}, {%8,%9}, {%0,%1,%2,%3};\n"
        : "+f"(c[0]), "+f"(c[1]), "+f"(c[2]), "+f"(c[3])
        : "r"(a[0]), "r"(a[1]), "r"(a[2]), "r"(a[3]), "r"(b0), "r"(b1));
}

__global__ __launch_bounds__(THREADS, 1)
void ffq_hmma_kernel(const float* __restrict__ x,
                     const float* __restrict__ theta,
                     const float* __restrict__ W1,
                     float* __restrict__ out) {
    extern __shared__ char sm[];
    const uint32_t sb = smem_u32(sm);

    const int tid  = threadIdx.x;
    const int warp = tid >> 5;
    const int lane = tid & 31;
    const int rowBase = blockIdx.x * BM;
    const int nBase   = blockIdx.y * BN;

    const int wm = warp >> 3;          // 0..1 -> 64 rows
    const int wn = warp & 7;           // 0..7 -> 32 cols

    // ---- per-thread q for its fixed row ----
    const int m   = tid >> 2;          // 0..127
    const int sub = tid & 3;           // 0..3  (16 H cols each)
    float qv[NQ];
    {
        const float* xr = x + (size_t)(rowBase + m) * EMBED;
        float4 x0 = *(const float4*)xr;
        float4 x1 = *(const float4*)(xr + 4);
        float xe[8] = {x0.x, x0.y, x0.z, x0.w, x1.x, x1.y, x1.z, x1.w};
        #pragma unroll
        for (int j = 0; j < NQ; ++j) qv[j] = cosf(2.0f * xe[j] + theta[j]);
    }

    float acc[4][4][4];
    #pragma unroll
    for (int mi = 0; mi < 4; ++mi)
        #pragma unroll
        for (int ni = 0; ni < 4; ++ni)
            #pragma unroll
            for (int r = 0; r < 4; ++r) acc[mi][ni][r] = 0.0f;

    // H compute helper (stage c -> buffer c&1)
    auto computeH = [&](int c) {
        const float* w1c = (const float*)(sm + W1S_OFF(c & 1));
        char* hrow = sm + HS_OFF(c & 1) + m * HKB;
        uint32_t hv[8];
        #pragma unroll
        for (int i = 0; i < 8; ++i) {
            const float* wp = w1c + sub * 128 + i * 16;
            float h0 = 0.0f, h1 = 0.0f;
            #pragma unroll
            for (int j = 0; j < NQ; ++j) {
                h0 = fmaf(qv[j], wp[j],     h0);
                h1 = fmaf(qv[j], wp[8 + j], h1);
            }
            __half2 p2 = __floats2half2_rn(fmaxf(h0, 0.0f), fmaxf(h1, 0.0f));
            hv[i] = *(uint32_t*)&p2;
        }
        *(uint4*)(hrow + sub * 32)      = make_uint4(hv[0], hv[1], hv[2], hv[3]);
        *(uint4*)(hrow + sub * 32 + 16) = make_uint4(hv[4], hv[5], hv[6], hv[7]);
    };

    auto loadW2 = [&](int c) {        // cp.async stage c -> buffer c&1
        const uint32_t dstB = sb + W2S_OFF(c & 1);
        #pragma unroll
        for (int i = 0; i < 4; ++i) {
            int idx = tid + i * THREADS;      // 0..2047
            int n = idx >> 3, cc = idx & 7;
            cp16(dstB + n * HKB + cc * 16,
                 W2h + (size_t)(nBase + n) * FFN + c * BK + cc * 8);
        }
        asm volatile("cp.async.commit_group;" ::: "memory");
    };

    auto loadW1 = [&](int c) {        // chunk c -> w1s[c&1]
        ((float*)(sm + W1S_OFF(c & 1)))[tid] = W1[c * (BK * NQ) + tid];
    };

    // ---- prologue: stage 0 ready, w1 chunks 0 & 1 in smem ----
    loadW1(0);
    loadW1(1);
    loadW2(0);
    __syncthreads();
    computeH(0);
    asm volatile("cp.async.wait_group 0;" ::: "memory");
    __syncthreads();

    const uint32_t aBase = sb + (wm * 64 + (lane & 15)) * HKB + ((lane >> 4) << 4);
    const uint32_t bBase = sb + (wn * 32 + ((lane >> 4) << 3) + (lane & 7)) * HKB
                              + (((lane >> 3) & 1) << 4);

    for (int kt = 0; kt < NCHUNK; ++kt) {
        const int p = kt & 1;
        if (kt + 1 < NCHUNK) {
            loadW2(kt + 1);          // tensor-idle LSU work
            computeH(kt + 1);        // FFMA pipe, overlaps HMMA below
        } else {
            asm volatile("cp.async.commit_group;" ::: "memory");
        }
        if (kt + 2 < NCHUNK) loadW1(kt + 2);

        // ---- MMA consume stage kt ----
        const uint32_t aS = aBase + HS_OFF(p);
        const uint32_t bS = bBase + W2S_OFF(p);
        #pragma unroll
        for (int ks = 0; ks < 4; ++ks) {
            uint32_t a[4][4], b[4][2];
            #pragma unroll
            for (int mi = 0; mi < 4; ++mi)
                ldsm_x4(a[mi], aS + mi * 16 * HKB + ks * 32);
            #pragma unroll
            for (int pr = 0; pr < 2; ++pr) {
                uint32_t r[4];
                ldsm_x4(r, bS + pr * 16 * HKB + ks * 32);
                b[2 * pr][0] = r[0]; b[2 * pr][1] = r[1];
                b[2 * pr + 1][0] = r[2]; b[2 * pr + 1][1] = r[3];
            }
            #pragma unroll
            for (int mi = 0; mi < 4; ++mi)
                #pragma unroll
                for (int ni = 0; ni < 4; ++ni)
                    mma16816(acc[mi][ni], a[mi], b[ni][0], b[ni][1]);
        }

        asm volatile("cp.async.wait_group 0;" ::: "memory");
        __syncthreads();
    }

    // ---- epilogue ----
    #pragma unroll
    for (int mi = 0; mi < 4; ++mi) {
        int row = rowBase + wm * 64 + mi * 16 + (lane >> 2);
        #pragma unroll
        for (int ni = 0; ni < 4; ++ni) {
            int col = nBase + wn * 32 + ni * 8 + 2 * (lane & 3);
            *(float2*)&out[(size_t)row * EMBED + col] =
                make_float2(acc[mi][ni][0], acc[mi][ni][1]);
            *(float2*)&out[(size_t)(row + 8) * EMBED + col] =
                make_float2(acc[mi][ni][2], acc[mi][ni][3]);
        }
    }
}

extern "C" void kernel_launch(void* const* d_in, const int* in_sizes, int n_in,
                              void* d_out, int out_size) {
    const float* x     = (const float*)d_in[0];
    const float* theta = (const float*)d_in[1];
    const float* W1    = (const float*)d_in[2];
    const float* W2    = (const float*)d_in[3];
    float* out = (float*)d_out;

    w2_convert_kernel<<<(EMBED * FFN / 2) / 256, 256>>>(W2);

    cudaFuncSetAttribute(ffq_hmma_kernel,
                         cudaFuncAttributeMaxDynamicSharedMemorySize, SMEM_BYTES);

    int rows = in_sizes[0] / EMBED;          // 32768
    dim3 grid(rows / BM, EMBED / BN);        // (256, 2)
    ffq_hmma_kernel<<<grid, THREADS, SMEM_BYTES>>>(x, theta, W1, out);
}

// round 6
// speedup vs baseline: 2.4263x; 2.4263x over previous
#include <cuda_runtime.h>
#include <cuda_fp16.h>
#include <stdint.h>

// q = cos(2*x[...,:8]+theta); h = relu(q@W1^T); out = h@W2^T
// HMMA mma.sync m16n8k16 (f16 in, f32 acc) + ldmatrix + cp.async double-buffer.

#define EMBED   512
#define FFN     2048
#define NQ      8
#define BM      128
#define BN      128
#define BK      64
#define NCHUNK  (FFN / BK)     // 32
#define THREADS 256
#define HKB     144            // padded row stride (72 halves) -> conflict-free

// dynamic smem (bytes)
#define HS_OFF(p)   ((p) * (BM * HKB))                    // 2 x 18432
#define W2S_OFF(p)  (2 * BM * HKB + (p) * (BN * HKB))     // 2 x 18432
#define W1S_OFF(p)  (4 * BM * HKB + (p) * 2048)           // 2 x 2048
#define SMEM_BYTES  (4 * BM * HKB + 2 * 2048)             // 77824

__device__ __half W2h[EMBED * FFN];   // fp16 W2 copy (2 MB, L2-resident)

__global__ void w2_convert_kernel(const float* __restrict__ W2) {
    int idx = blockIdx.x * 256 + threadIdx.x;
    float2 v = *(const float2*)&W2[idx * 2];
    *(__half2*)&W2h[idx * 2] = __floats2half2_rn(v.x, v.y);
}

__device__ __forceinline__ uint32_t smem_u32(const void* p) {
    uint32_t a;
    asm("{ .reg .u64 t; cvta.to.shared.u64 t, %1; cvt.u32.u64 %0, t; }" : "=r"(a) : "l"(p));
    return a;
}
__device__ __forceinline__ void ldsm_x4(uint32_t* r, uint32_t addr) {
    asm volatile("ldmatrix.sync.aligned.m8n8.x4.shared.b16 {%0,%1,%2,%3}, [%4];"
                 : "=r"(r[0]), "=r"(r[1]), "=r"(r[2]), "=r"(r[3]) : "r"(addr));
}
__device__ __forceinline__ void cp16(uint32_t dst, const void* src) {
    asm volatile("cp.async.cg.shared.global [%0], [%1], 16;" :: "r"(dst), "l"(src));
}
__device__ __forceinline__ void mma16816(float* c, const uint32_t* a,
                                         uint32_t b0, uint32_t b1) {
    asm volatile(
        "mma.sync.aligned.m16n8k16.row.col.f32.f16.f16.f32 "
        "{%0,%1,%2,%3}, {%4,%5,%6,%7}, {%8,%9}, {%0,%1,%2,%3};\n"
        : "+f"(c[0]), "+f"(c[1]), "+f"(c[2]), "+f"(c[3])
        : "r"(a[0]), "r"(a[1]), "r"(a[2]), "r"(a[3]), "r"(b0), "r"(b1));
}

__global__ __launch_bounds__(THREADS, 2)
void ffq_hmma_kernel(const float* __restrict__ x,
                     const float* __restrict__ theta,
                     const float* __restrict__ W1,
                     float* __restrict__ out) {
    extern __shared__ char sm[];
    const uint32_t sb = smem_u32(sm);

    const int tid  = threadIdx.x;
    const int warp = tid >> 5;
    const int lane = tid & 31;
    const int rowBase = blockIdx.x * BM;
    const int nBase   = blockIdx.y * BN;

    const int wm = warp >> 2;            // 0..1 -> 64 rows
    const int wn = warp & 3;             // 0..3 -> 32 cols
    const int moff = wm * 64;

    // ---- per-thread q (2 threads per row) ----
    const int m = tid >> 1;              // 0..127
    const int h = tid & 1;
    float qv[NQ];
    {
        const float* xr = x + (size_t)(rowBase + m) * EMBED;
        float4 x0 = *(const float4*)xr;
        float4 x1 = *(const float4*)(xr + 4);
        float xe[8] = {x0.x, x0.y, x0.z, x0.w, x1.x, x1.y, x1.z, x1.w};
        #pragma unroll
        for (int j = 0; j < NQ; ++j) qv[j] = cosf(2.0f * xe[j] + theta[j]);
    }

    float acc[4][4][4];
    #pragma unroll
    for (int mi = 0; mi < 4; ++mi)
        #pragma unroll
        for (int ni = 0; ni < 4; ++ni)
            #pragma unroll
            for (int r = 0; r < 4; ++r) acc[mi][ni][r] = 0.0f;

    auto loadW1 = [&](int c) {           // W1 chunk c -> slot c&1 (as-is layout)
        float* d = (float*)(sm + W1S_OFF(c & 1));
        d[tid]        = W1[c * 512 + tid];
        d[tid + 256]  = W1[c * 512 + tid + 256];
    };
    auto loadW2 = [&](int c) {           // cp.async stage c -> buf c&1
        const uint32_t dstB = sb + W2S_OFF(c & 1);
        #pragma unroll
        for (int i = 0; i < 4; ++i) {
            int idx = tid + i * THREADS;           // 0..1023
            int n = idx >> 3, cc = idx & 7;
            cp16(dstB + n * HKB + cc * 16,
                 W2h + (size_t)(nBase + n) * FFN + c * BK + cc * 8);
        }
        asm volatile("cp.async.commit_group;" ::: "memory");
    };
    auto computeH = [&](int c) {         // H chunk c -> buf c&1
        const float* w1c = (const float*)(sm + W1S_OFF(c & 1));
        char* hrow = sm + HS_OFF(c & 1) + m * HKB;
        #pragma unroll
        for (int i = 0; i < 16; ++i) {
            int p = h + 2 * i;                     // k-pair (2p, 2p+1)
            const float4* wq = (const float4*)(w1c + 16 * p);
            float4 w0 = wq[0], w1v = wq[1], w2v = wq[2], w3v = wq[3];
            float h0 = qv[0]*w0.x + qv[1]*w0.y + qv[2]*w0.z + qv[3]*w0.w
                     + qv[4]*w1v.x + qv[5]*w1v.y + qv[6]*w1v.z + qv[7]*w1v.w;
            float h1 = qv[0]*w2v.x + qv[1]*w2v.y + qv[2]*w2v.z + qv[3]*w2v.w
                     + qv[4]*w3v.x + qv[5]*w3v.y + qv[6]*w3v.z + qv[7]*w3v.w;
            *(__half2*)(hrow + 4 * p) =
                __floats2half2_rn(fmaxf(h0, 0.0f), fmaxf(h1, 0.0f));
        }
    };

    // ---- prologue ----
    loadW1(0);
    __syncthreads();
    loadW2(0);
    computeH(0);
    loadW1(1);
    asm volatile("cp.async.wait_group 0;" ::: "memory");
    __syncthreads();

    // ldmatrix lane addresses
    const uint32_t aOff = (moff + (lane & 15)) * HKB + ((lane >> 4) << 4);
    const uint32_t bOff = (wn * 32 + ((lane >> 4) << 3) + (lane & 7)) * HKB
                          + (((lane >> 3) & 1) << 4);

    for (int kt = 0; kt < NCHUNK; ++kt) {
        const int p = kt & 1;
        if (kt + 1 < NCHUNK) {
            loadW2(kt + 1);          // LSU, overlaps HMMA below
            computeH(kt + 1);        // FMA pipe, overlaps HMMA below
        }
        if (kt + 2 < NCHUNK) loadW1(kt + 2);

        const uint32_t aS = sb + HS_OFF(p)  + aOff;
        const uint32_t bS = sb + W2S_OFF(p) + bOff;
        #pragma unroll
        for (int ks = 0; ks < 4; ++ks) {
            uint32_t b[4][2];
            {
                uint32_t r[4];
                ldsm_x4(r, bS + ks * 32);
                b[0][0] = r[0]; b[0][1] = r[1]; b[1][0] = r[2]; b[1][1] = r[3];
                ldsm_x4(r, bS + 16 * HKB + ks * 32);
                b[2][0] = r[0]; b[2][1] = r[1]; b[3][0] = r[2]; b[3][1] = r[3];
            }
            #pragma unroll
            for (int mi = 0; mi < 4; ++mi) {
                uint32_t a[4];
                ldsm_x4(a, aS + mi * 16 * HKB + ks * 32);
                #pragma unroll
                for (int ni = 0; ni < 4; ++ni)
                    mma16816(acc[mi][ni], a, b[ni][0], b[ni][1]);
            }
        }

        if (kt + 1 < NCHUNK)
            asm volatile("cp.async.wait_group 0;" ::: "memory");
        __syncthreads();
    }

    // ---- epilogue ----
    #pragma unroll
    for (int mi = 0; mi < 4; ++mi) {
        int row = rowBase + moff + mi * 16 + (lane >> 2);
        #pragma unroll
        for (int ni = 0; ni < 4; ++ni) {
            int col = nBase + wn * 32 + ni * 8 + 2 * (lane & 3);
            *(float2*)&out[(size_t)row * EMBED + col] =
                make_float2(acc[mi][ni][0], acc[mi][ni][1]);
            *(float2*)&out[(size_t)(row + 8) * EMBED + col] =
                make_float2(acc[mi][ni][2], acc[mi][ni][3]);
        }
    }
}

extern "C" void kernel_launch(void* const* d_in, const int* in_sizes, int n_in,
                              void* d_out, int out_size) {
    const float* x     = (const float*)d_in[0];
    const float* theta = (const float*)d_in[1];
    const float* W1    = (const float*)d_in[2];
    const float* W2    = (const float*)d_in[3];
    float* out = (float*)d_out;

    w2_convert_kernel<<<(EMBED * FFN / 2) / 256, 256>>>(W2);

    cudaFuncSetAttribute(ffq_hmma_kernel,
                         cudaFuncAttributeMaxDynamicSharedMemorySize, SMEM_BYTES);

    int rows = in_sizes[0] / EMBED;          // 32768
    dim3 grid(rows / BM, EMBED / BN);        // (256, 4)
    ffq_hmma_kernel<<<grid, THREADS, SMEM_BYTES>>>(x, theta, W1, out);
}

// round 7
// speedup vs baseline: 3.3050x; 1.3622x over previous
#include <cuda_runtime.h>
#include <cuda_fp16.h>
#include <stdint.h>

// q = cos(2*x[...,:8]+theta); h = relu(q@W1^T); out = h@W2^T
// Two-phase: (A) H precompute -> global fp16; (B) pure HMMA GEMM out = H @ W2^T.

#define EMBED   512
#define FFN     2048
#define NQ      8
#define ROWS_T  32768
#define BM      128
#define BN      128
#define BK      64
#define NCHUNK  (FFN / BK)     // 32
#define HKB     144            // padded smem row stride bytes (72 halves)

// kernel B dynamic smem
#define HS_OFF(p)   ((p) * (BM * HKB))                    // 2 x 18432
#define W2S_OFF(p)  (2 * BM * HKB + (p) * (BN * HKB))     // 2 x 18432
#define SMEM_B      (4 * BM * HKB)                        // 73728

__device__ __half W2h[EMBED * FFN];          // fp16 W2 (2 MB, L2-resident)
__device__ __half Hg[(size_t)ROWS_T * FFN];  // fp16 H   (128 MB)

// ---------------- helpers ----------------
__device__ __forceinline__ uint32_t smem_u32(const void* p) {
    uint32_t a;
    asm("{ .reg .u64 t; cvta.to.shared.u64 t, %1; cvt.u32.u64 %0, t; }" : "=r"(a) : "l"(p));
    return a;
}
__device__ __forceinline__ void ldsm_x4(uint32_t* r, uint32_t addr) {
    asm volatile("ldmatrix.sync.aligned.m8n8.x4.shared.b16 {%0,%1,%2,%3}, [%4];"
                 : "=r"(r[0]), "=r"(r[1]), "=r"(r[2]), "=r"(r[3]) : "r"(addr));
}
__device__ __forceinline__ void cp16(uint32_t dst, const void* src) {
    asm volatile("cp.async.cg.shared.global [%0], [%1], 16;" :: "r"(dst), "l"(src));
}
__device__ __forceinline__ void mma16816(float* c, const uint32_t* a,
                                         uint32_t b0, uint32_t b1) {
    asm volatile(
        "mma.sync.aligned.m16n8k16.row.col.f32.f16.f16.f32 "
        "{%0,%1,%2,%3}, {%4,%5,%6,%7}, {%8,%9}, {%0,%1,%2,%3};\n"
        : "+f"(c[0]), "+f"(c[1]), "+f"(c[2]), "+f"(c[3])
        : "r"(a[0]), "r"(a[1]), "r"(a[2]), "r"(a[3]), "r"(b0), "r"(b1));
}

// ---------------- W2 f32 -> fp16 ----------------
__global__ void w2_convert_kernel(const float* __restrict__ W2) {
    int idx = blockIdx.x * 256 + threadIdx.x;
    float2 v = *(const float2*)&W2[idx * 2];
    *(__half2*)&W2h[idx * 2] = __floats2half2_rn(v.x, v.y);
}

// ---------------- kernel A: H precompute ----------------
// block: 256 threads, 64 rows. Thread owns 8 contiguous k-cols (W1 in regs),
// loops rows reading q from smem (broadcast).
__global__ __launch_bounds__(256)
void h_precompute_kernel(const float* __restrict__ x,
                         const float* __restrict__ theta,
                         const float* __restrict__ W1) {
    __shared__ float qs[64][NQ];
    const int tid = threadIdx.x;
    const int rowBase = blockIdx.x * 64;

    // W1 slice -> regs: k in [8*tid, 8*tid+8), w[i][j]
    float w[8][8];
    {
        const float4* src = (const float4*)(W1 + tid * 64);
        #pragma unroll
        for (int i = 0; i < 8; ++i) {
            float4 a = src[2 * i], b = src[2 * i + 1];
            w[i][0] = a.x; w[i][1] = a.y; w[i][2] = a.z; w[i][3] = a.w;
            w[i][4] = b.x; w[i][5] = b.y; w[i][6] = b.z; w[i][7] = b.w;
        }
    }
    // q for 64 rows
    #pragma unroll
    for (int v = 0; v < 2; ++v) {
        int idx = tid + v * 256;
        int r = idx >> 3, j = idx & 7;
        float xv = x[(size_t)(rowBase + r) * EMBED + j];
        qs[r][j] = cosf(2.0f * xv + theta[j]);
    }
    __syncthreads();

    for (int r = 0; r < 64; ++r) {
        float4 q0 = *(const float4*)&qs[r][0];
        float4 q1 = *(const float4*)&qs[r][4];
        float qv[8] = {q0.x, q0.y, q0.z, q0.w, q1.x, q1.y, q1.z, q1.w};
        uint32_t hv[4];
        #pragma unroll
        for (int i2 = 0; i2 < 4; ++i2) {
            float h0 = 0.f, h1 = 0.f;
            #pragma unroll
            for (int j = 0; j < 8; ++j) {
                h0 = fmaf(qv[j], w[2 * i2][j],     h0);
                h1 = fmaf(qv[j], w[2 * i2 + 1][j], h1);
            }
            __half2 p = __floats2half2_rn(fmaxf(h0, 0.f), fmaxf(h1, 0.f));
            hv[i2] = *(uint32_t*)&p;
        }
        *(uint4*)&Hg[(size_t)(rowBase + r) * FFN + tid * 8] =
            make_uint4(hv[0], hv[1], hv[2], hv[3]);
    }
}

// ---------------- kernel B: GEMM out = H @ W2^T ----------------
// 128 threads, 4 warps, warp tile 64x64 (2x2), double-buffered cp.async.
__global__ __launch_bounds__(128)
void gemm_kernel(float* __restrict__ out) {
    extern __shared__ char sm[];
    const uint32_t sb = smem_u32(sm);

    const int tid  = threadIdx.x;
    const int warp = tid >> 5;
    const int lane = tid & 31;
    const int nBase   = blockIdx.x * BN;     // n fastest -> L2 reuse of H
    const int rowBase = blockIdx.y * BM;

    const int wm = warp >> 1;                // 0..1
    const int wn = warp & 1;                 // 0..1

    float acc[4][8][4];
    #pragma unroll
    for (int mi = 0; mi < 4; ++mi)
        #pragma unroll
        for (int ni = 0; ni < 8; ++ni)
            #pragma unroll
            for (int r = 0; r < 4; ++r) acc[mi][ni][r] = 0.0f;

    auto stage = [&](int c) {
        const int p = c & 1;
        const uint32_t hD  = sb + HS_OFF(p);
        const uint32_t w2D = sb + W2S_OFF(p);
        #pragma unroll
        for (int i = 0; i < 8; ++i) {
            int idx = tid + i * 128;               // 0..1023
            int n = idx >> 3, cc = idx & 7;
            cp16(hD + n * HKB + cc * 16,
                 Hg + (size_t)(rowBase + n) * FFN + c * BK + cc * 8);
            cp16(w2D + n * HKB + cc * 16,
                 W2h + (size_t)(nBase + n) * FFN + c * BK + cc * 8);
        }
        asm volatile("cp.async.commit_group;" ::: "memory");
    };

    stage(0);
    asm volatile("cp.async.wait_group 0;" ::: "memory");
    __syncthreads();

    const uint32_t aOff = (wm * 64 + (lane & 15)) * HKB + ((lane >> 4) << 4);
    const uint32_t bOff = (wn * 64 + ((lane >> 4) << 3) + (lane & 7)) * HKB
                          + (((lane >> 3) & 1) << 4);

    for (int kt = 0; kt < NCHUNK; ++kt) {
        const int p = kt & 1;
        if (kt + 1 < NCHUNK) stage(kt + 1);

        const uint32_t aS = sb + HS_OFF(p)  + aOff;
        const uint32_t bS = sb + W2S_OFF(p) + bOff;
        #pragma unroll
        for (int ks = 0; ks < 4; ++ks) {
            uint32_t b[8][2];
            #pragma unroll
            for (int pr = 0; pr < 4; ++pr) {
                uint32_t r[4];
                ldsm_x4(r, bS + pr * 16 * HKB + ks * 32);
                b[2 * pr][0] = r[0]; b[2 * pr][1] = r[1];
                b[2 * pr + 1][0] = r[2]; b[2 * pr + 1][1] = r[3];
            }
            #pragma unroll
            for (int mi = 0; mi < 4; ++mi) {
                uint32_t a[4];
                ldsm_x4(a, aS + mi * 16 * HKB + ks * 32);
                #pragma unroll
                for (int ni = 0; ni < 8; ++ni)
                    mma16816(acc[mi][ni], a, b[ni][0], b[ni][1]);
            }
        }

        if (kt + 1 < NCHUNK)
            asm volatile("cp.async.wait_group 0;" ::: "memory");
        __syncthreads();
    }

    #pragma unroll
    for (int mi = 0; mi < 4; ++mi) {
        int row = rowBase + wm * 64 + mi * 16 + (lane >> 2);
        #pragma unroll
        for (int ni = 0; ni < 8; ++ni) {
            int col = nBase + wn * 64 + ni * 8 + 2 * (lane & 3);
            *(float2*)&out[(size_t)row * EMBED + col] =
                make_float2(acc[mi][ni][0], acc[mi][ni][1]);
            *(float2*)&out[(size_t)(row + 8) * EMBED + col] =
                make_float2(acc[mi][ni][2], acc[mi][ni][3]);
        }
    }
}

extern "C" void kernel_launch(void* const* d_in, const int* in_sizes, int n_in,
                              void* d_out, int out_size) {
    const float* x     = (const float*)d_in[0];
    const float* theta = (const float*)d_in[1];
    const float* W1    = (const float*)d_in[2];
    const float* W2    = (const float*)d_in[3];
    float* out = (float*)d_out;

    int rows = in_sizes[0] / EMBED;              // 32768

    w2_convert_kernel<<<(EMBED * FFN / 2) / 256, 256>>>(W2);
    h_precompute_kernel<<<rows / 64, 256>>>(x, theta, W1);

    cudaFuncSetAttribute(gemm_kernel,
                         cudaFuncAttributeMaxDynamicSharedMemorySize, SMEM_B);
    dim3 grid(EMBED / BN, rows / BM);            // (4, 256), n fastest
    gemm_kernel<<<grid, 128, SMEM_B>>>(out);
}